// round 2
// baseline (speedup 1.0000x reference)
#include <cuda_runtime.h>

#define TSEQ  128
#define BATCH 4096

// Inter-layer sequence scratch (static device globals; no allocation anywhere).
// seq3 aliases the front of seq1: L3 reads seq2 and writes seq3; seq1 is dead by then.
__device__ float d_seq1[(size_t)BATCH * TSEQ * 128]; // L1 out [B,T,128]; front reused as L3 out [B,T,32]
__device__ float d_seq2[(size_t)BATCH * TSEQ * 64];  // L2 out [B,T,64]
__device__ float d_h4[BATCH * 8];                    // L4 final states [B,8]

__device__ __forceinline__ float fsig(float x) {
    return 1.0f / (1.0f + __expf(-x));
}
__device__ __forceinline__ float ftanh(float x) {
    // 1 - 2/(e^{2x}+1): saturates cleanly at +/-1, no inf/inf
    float e = __expf(2.0f * x);
    return 1.0f - 2.0f / (e + 1.0f);
}

// Buffer tags: 0 = kernel param, 1 = d_seq1, 2 = d_seq2, 3 = d_seq1 (as L3 out), 4 = d_h4
template<int TAG>
__device__ __forceinline__ float* buf_ptr(float* param) {
    if (TAG == 1 || TAG == 3) return d_seq1;
    if (TAG == 2) return d_seq2;
    if (TAG == 4) return d_h4;
    return param;
}

// Fused bidirectional LSTM layer.
//   grid = (BATCH/BT, 2)  [y: 0=forward, 1=backward]
//   Each CTA: BT batch rows, all T timesteps. Weights + h tile in smem, c in regs.
//   Thread (tj, tb): output columns jh0=tj*2, jh0+1 (each with 4 gates -> 8 accs)
//   for BPT batch rows. Smem weights permuted to [k][jh*4 + gate] so the 8
//   columns are contiguous (two LDS.128 per k).
template<int D, int H, int BT, int BPT, bool LAST, int SRC, int DST>
__global__ void __launch_bounds__((H / 2) * (BT / BPT))
lstm_layer(float* __restrict__ in_param, float* __restrict__ out_param,
           const float* __restrict__ WkF, const float* __restrict__ WrF, const float* __restrict__ bF,
           const float* __restrict__ WkB, const float* __restrict__ WrB, const float* __restrict__ bB)
{
    constexpr int NG = 4 * H;
    constexpr int TJ = NG / 8;       // threads along j (= H/2)
    constexpr int TB = BT / BPT;     // threads along batch
    constexpr int NT = TJ * TB;
    constexpr int DS = (D % 2 == 0) ? D + 1 : D;  // padded strides (bank conflicts)
    constexpr int HS = H + 1;

    const float* in = buf_ptr<SRC>(in_param);
    float* out = buf_ptr<DST>(out_param);

    extern __shared__ float sm[];
    float* sWk = sm;                 // [D][NG] permuted
    float* sWr = sWk + D * NG;       // [H][NG] permuted
    float* sB  = sWr + H * NG;       // [NG]    permuted
    float* sH  = sB + NG;            // [BT][HS]
    float* sX  = sH + BT * HS;       // [BT][DS]

    const int tid = threadIdx.x;
    const int tj  = tid % TJ;
    const int tb  = tid / TJ;
    const bool fwd = (blockIdx.y == 0);
    const float* Wk = fwd ? WkF : WkB;
    const float* Wr = fwd ? WrF : WrB;
    const float* bv = fwd ? bF  : bB;
    const int b0 = blockIdx.x * BT;

    // Load + permute weights: new col = jh*4+g  <-  old col = g*H+jh
    for (int i = tid; i < D * NG; i += NT) {
        int k = i / NG, col = i - k * NG;
        sWk[i] = Wk[k * NG + (col & 3) * H + (col >> 2)];
    }
    for (int i = tid; i < H * NG; i += NT) {
        int k = i / NG, col = i - k * NG;
        sWr[i] = Wr[k * NG + (col & 3) * H + (col >> 2)];
    }
    for (int i = tid; i < NG; i += NT)
        sB[i] = bv[(i & 3) * H + (i >> 2)];
    for (int i = tid; i < BT * HS; i += NT) sH[i] = 0.0f;
    __syncthreads();

    float bj[8];
#pragma unroll
    for (int q = 0; q < 8; q++) bj[q] = sB[tj * 8 + q];

    float cst[BPT][2];
#pragma unroll
    for (int bi = 0; bi < BPT; bi++) { cst[bi][0] = 0.0f; cst[bi][1] = 0.0f; }
    float hlast[BPT][2];
#pragma unroll
    for (int bi = 0; bi < BPT; bi++) { hlast[bi][0] = 0.0f; hlast[bi][1] = 0.0f; }

    const int jh0 = tj * 2;
    const float* wk = sWk + tj * 8;
    const float* wr = sWr + tj * 8;

    for (int s = 0; s < TSEQ; s++) {
        const int t = fwd ? s : (TSEQ - 1 - s);

        // stage x_t tile for this CTA's batch rows
        {
            const float* inb = in + ((size_t)b0 * TSEQ + t) * D;
            for (int i = tid; i < BT * D; i += NT) {
                int b = i / D, k = i - b * D;
                sX[b * DS + k] = inb[(size_t)b * TSEQ * D + k];
            }
        }
        __syncthreads();   // sX staged + previous-step sH writes visible

        float acc[BPT][8];
#pragma unroll
        for (int bi = 0; bi < BPT; bi++)
#pragma unroll
            for (int q = 0; q < 8; q++) acc[bi][q] = bj[q];

        // z += x_t @ Wk
#pragma unroll 4
        for (int k = 0; k < D; k++) {
            float4 w0 = *(const float4*)(wk + k * NG);
            float4 w1 = *(const float4*)(wk + k * NG + 4);
#pragma unroll
            for (int bi = 0; bi < BPT; bi++) {
                float v = sX[(tb * BPT + bi) * DS + k];
                acc[bi][0] = fmaf(v, w0.x, acc[bi][0]);
                acc[bi][1] = fmaf(v, w0.y, acc[bi][1]);
                acc[bi][2] = fmaf(v, w0.z, acc[bi][2]);
                acc[bi][3] = fmaf(v, w0.w, acc[bi][3]);
                acc[bi][4] = fmaf(v, w1.x, acc[bi][4]);
                acc[bi][5] = fmaf(v, w1.y, acc[bi][5]);
                acc[bi][6] = fmaf(v, w1.z, acc[bi][6]);
                acc[bi][7] = fmaf(v, w1.w, acc[bi][7]);
            }
        }
        // z += h_{t-1} @ Wr
#pragma unroll 4
        for (int k = 0; k < H; k++) {
            float4 w0 = *(const float4*)(wr + k * NG);
            float4 w1 = *(const float4*)(wr + k * NG + 4);
#pragma unroll
            for (int bi = 0; bi < BPT; bi++) {
                float v = sH[(tb * BPT + bi) * HS + k];
                acc[bi][0] = fmaf(v, w0.x, acc[bi][0]);
                acc[bi][1] = fmaf(v, w0.y, acc[bi][1]);
                acc[bi][2] = fmaf(v, w0.z, acc[bi][2]);
                acc[bi][3] = fmaf(v, w0.w, acc[bi][3]);
                acc[bi][4] = fmaf(v, w1.x, acc[bi][4]);
                acc[bi][5] = fmaf(v, w1.y, acc[bi][5]);
                acc[bi][6] = fmaf(v, w1.z, acc[bi][6]);
                acc[bi][7] = fmaf(v, w1.w, acc[bi][7]);
            }
        }
        __syncthreads();   // everyone done reading old sH / sX

        // gates: [i, f, g, o] per hidden unit; update c (regs) and h (smem/out)
#pragma unroll
        for (int bi = 0; bi < BPT; bi++) {
            const int b = tb * BPT + bi;
            float h2[2];
#pragma unroll
            for (int jj = 0; jj < 2; jj++) {
                float zi = acc[bi][jj * 4 + 0];
                float zf = acc[bi][jj * 4 + 1];
                float zg = acc[bi][jj * 4 + 2];
                float zo = acc[bi][jj * 4 + 3];
                float cc = fsig(zf) * cst[bi][jj] + fsig(zi) * ftanh(zg);
                cst[bi][jj] = cc;
                h2[jj] = fsig(zo) * ftanh(cc);
                sH[b * HS + jh0 + jj] = h2[jj];
            }
            if (LAST) {
                hlast[bi][0] = h2[0];
                hlast[bi][1] = h2[1];
            } else {
                float2 hv = make_float2(h2[0], h2[1]);
                *(float2*)(out + ((size_t)(b0 + b) * TSEQ + t) * (2 * H)
                               + (fwd ? 0 : H) + jh0) = hv;
            }
        }
        __syncthreads();   // new sH published before next step's GEMM
    }

    if (LAST) {
#pragma unroll
        for (int bi = 0; bi < BPT; bi++) {
            const int b = b0 + tb * BPT + bi;
            out[(size_t)b * (2 * H) + (fwd ? 0 : H) + jh0]     = hlast[bi][0];
            out[(size_t)b * (2 * H) + (fwd ? 0 : H) + jh0 + 1] = hlast[bi][1];
        }
    }
}

__global__ void dense_sig(const float* __restrict__ W,
                          const float* __restrict__ bb, float* __restrict__ out)
{
    int b = blockIdx.x * blockDim.x + threadIdx.x;
    if (b >= BATCH) return;
    const float* hr = d_h4 + (size_t)b * 8;
    float hv[8];
#pragma unroll
    for (int j = 0; j < 8; j++) hv[j] = hr[j];
#pragma unroll
    for (int m = 0; m < 3; m++) {
        float a = bb[m];
#pragma unroll
        for (int j = 0; j < 8; j++) a = fmaf(hv[j], W[j * 3 + m], a);
        out[(size_t)b * 3 + m] = fsig(a);
    }
}

static size_t smem_bytes(int D, int H, int BT) {
    int NG = 4 * H;
    int DS = (D % 2 == 0) ? D + 1 : D;
    int HS = H + 1;
    return (size_t)(D * NG + H * NG + NG + BT * HS + BT * DS) * sizeof(float);
}

extern "C" void kernel_launch(void* const* d_in, const int* in_sizes, int n_in,
                              void* d_out, int out_size)
{
    (void)in_sizes; (void)n_in; (void)out_size;
    float* x = (float*)d_in[0];
    // layer param order per layer: Wk, Wr, b for f then b
    const float* p[24];
    for (int i = 0; i < 24; i++) p[i] = (const float*)d_in[1 + i];
    const float* dW = (const float*)d_in[25];
    const float* db = (const float*)d_in[26];

    size_t s1 = smem_bytes(78, 64, 64);
    size_t s2 = smem_bytes(128, 32, 64);
    size_t s3 = smem_bytes(64, 16, 64);
    size_t s4 = smem_bytes(32, 4, 128);
    cudaFuncSetAttribute(lstm_layer<78, 64, 64, 8, false, 0, 1>,
                         cudaFuncAttributeMaxDynamicSharedMemorySize, (int)s1);
    cudaFuncSetAttribute(lstm_layer<128, 32, 64, 4, false, 1, 2>,
                         cudaFuncAttributeMaxDynamicSharedMemorySize, (int)s2);
    cudaFuncSetAttribute(lstm_layer<64, 16, 64, 2, false, 2, 3>,
                         cudaFuncAttributeMaxDynamicSharedMemorySize, (int)s3);
    cudaFuncSetAttribute(lstm_layer<32, 4, 128, 2, true, 3, 4>,
                         cudaFuncAttributeMaxDynamicSharedMemorySize, (int)s4);

    // L1: x -> seq1 (78 -> 2*64), grid (64,2), 256 thr
    lstm_layer<78, 64, 64, 8, false, 0, 1><<<dim3(BATCH / 64, 2), 256, s1>>>(
        x, nullptr, p[0], p[1], p[2], p[3], p[4], p[5]);
    // L2: seq1 -> seq2 (128 -> 2*32)
    lstm_layer<128, 32, 64, 4, false, 1, 2><<<dim3(BATCH / 64, 2), 256, s2>>>(
        nullptr, nullptr, p[6], p[7], p[8], p[9], p[10], p[11]);
    // L3: seq2 -> seq3(=seq1 front) (64 -> 2*16)
    lstm_layer<64, 16, 64, 2, false, 2, 3><<<dim3(BATCH / 64, 2), 256, s3>>>(
        nullptr, nullptr, p[12], p[13], p[14], p[15], p[16], p[17]);
    // L4: seq3 -> h4 final states [B,8] (32 -> 2*4)
    lstm_layer<32, 4, 128, 2, true, 3, 4><<<dim3(BATCH / 128, 2), 128, s4>>>(
        nullptr, nullptr, p[18], p[19], p[20], p[21], p[22], p[23]);
    // dense 8->3 + sigmoid
    dense_sig<<<(BATCH + 255) / 256, 256>>>(dW, db, (float*)d_out);
}

// round 5
// speedup vs baseline: 1.0336x; 1.0336x over previous
#include <cuda_runtime.h>

#define TSEQ  128
#define BATCH 4096

// Inter-layer sequence scratch (static device globals; no allocation anywhere).
// L3 output aliases the front of d_seq1 (seq1 is dead once L2 finished reading it).
__device__ float d_seq1[(size_t)BATCH * TSEQ * 128]; // L1 out [B,T,128]; front reused as L3 out [B,T,32]
__device__ float d_seq2[(size_t)BATCH * TSEQ * 64];  // L2 out [B,T,64]
__device__ float d_h4[BATCH * 8];                    // L4 final states [B,8]

__device__ __forceinline__ float fsig(float x) {
    return 1.0f / (1.0f + __expf(-x));
}
__device__ __forceinline__ float ftanh(float x) {
    // 1 - 2/(e^{2x}+1): saturates cleanly at +/-1, no inf/inf
    float e = __expf(2.0f * x);
    return 1.0f - 2.0f / (e + 1.0f);
}

// Buffer tags: 0 = kernel param, 1 = d_seq1, 2 = d_seq2, 3 = d_seq1 (as L3 out)
template<int TAG>
__device__ __forceinline__ float* buf_ptr(float* param) {
    if (TAG == 1 || TAG == 3) return d_seq1;
    if (TAG == 2) return d_seq2;
    return param;
}

// Fused bidirectional LSTM layer (layers 1-3).
//   grid = (BATCH/BT, 2)  [y: 0=forward, 1=backward]
//   Each CTA: BT batch rows, all T timesteps. Weights + h tile in smem, c in regs.
//   Thread (tj, tb): 8 gate columns (2 hidden units x 4 gates) for BPT batch rows.
//   Weights permuted in smem to [k][jh*4+gate] so the 8 columns are contiguous
//   (two LDS.128 per k).
template<int D, int H, int BT, int BPT, int SRC, int DST>
__global__ void __launch_bounds__((H / 2) * (BT / BPT))
lstm_layer(float* __restrict__ in_param, float* __restrict__ out_param,
           const float* __restrict__ WkF, const float* __restrict__ WrF, const float* __restrict__ bF,
           const float* __restrict__ WkB, const float* __restrict__ WrB, const float* __restrict__ bB)
{
    constexpr int NG = 4 * H;
    constexpr int TJ = NG / 8;       // threads along j (= H/2)
    constexpr int TB = BT / BPT;     // threads along batch
    constexpr int NT = TJ * TB;
    constexpr int DS = (D % 2 == 0) ? D + 1 : D;  // padded strides (bank conflicts)
    constexpr int HS = H + 1;

    const float* in = buf_ptr<SRC>(in_param);
    float* out = buf_ptr<DST>(out_param);

    extern __shared__ float sm[];
    float* sWk = sm;                 // [D][NG] permuted
    float* sWr = sWk + D * NG;       // [H][NG] permuted
    float* sB  = sWr + H * NG;       // [NG]    permuted
    float* sH  = sB + NG;            // [BT][HS]
    float* sX  = sH + BT * HS;       // [BT][DS]

    const int tid = threadIdx.x;
    const int tj  = tid % TJ;
    const int tb  = tid / TJ;
    const bool fwd = (blockIdx.y == 0);
    const float* Wk = fwd ? WkF : WkB;
    const float* Wr = fwd ? WrF : WrB;
    const float* bv = fwd ? bF  : bB;
    const int b0 = blockIdx.x * BT;

    // Load + permute weights: new col = jh*4+g  <-  old col = g*H+jh
    for (int i = tid; i < D * NG; i += NT) {
        int k = i / NG, col = i - k * NG;
        sWk[i] = Wk[k * NG + (col & 3) * H + (col >> 2)];
    }
    for (int i = tid; i < H * NG; i += NT) {
        int k = i / NG, col = i - k * NG;
        sWr[i] = Wr[k * NG + (col & 3) * H + (col >> 2)];
    }
    for (int i = tid; i < NG; i += NT)
        sB[i] = bv[(i & 3) * H + (i >> 2)];
    for (int i = tid; i < BT * HS; i += NT) sH[i] = 0.0f;
    __syncthreads();

    float bj[8];
#pragma unroll
    for (int q = 0; q < 8; q++) bj[q] = sB[tj * 8 + q];

    float cst[BPT][2];
#pragma unroll
    for (int bi = 0; bi < BPT; bi++) { cst[bi][0] = 0.0f; cst[bi][1] = 0.0f; }

    const int jh0 = tj * 2;
    const float* wk = sWk + tj * 8;
    const float* wr = sWr + tj * 8;

    for (int s = 0; s < TSEQ; s++) {
        const int t = fwd ? s : (TSEQ - 1 - s);

        // stage x_t tile for this CTA's batch rows
        {
            const float* inb = in + ((size_t)b0 * TSEQ + t) * D;
            for (int i = tid; i < BT * D; i += NT) {
                int b = i / D, k = i - b * D;
                sX[b * DS + k] = inb[(size_t)b * TSEQ * D + k];
            }
        }
        __syncthreads();   // sX staged + previous-step sH writes visible

        float acc[BPT][8];
#pragma unroll
        for (int bi = 0; bi < BPT; bi++)
#pragma unroll
            for (int q = 0; q < 8; q++) acc[bi][q] = bj[q];

        // z += x_t @ Wk
#pragma unroll 4
        for (int k = 0; k < D; k++) {
            float4 w0 = *(const float4*)(wk + k * NG);
            float4 w1 = *(const float4*)(wk + k * NG + 4);
#pragma unroll
            for (int bi = 0; bi < BPT; bi++) {
                float v = sX[(tb * BPT + bi) * DS + k];
                acc[bi][0] = fmaf(v, w0.x, acc[bi][0]);
                acc[bi][1] = fmaf(v, w0.y, acc[bi][1]);
                acc[bi][2] = fmaf(v, w0.z, acc[bi][2]);
                acc[bi][3] = fmaf(v, w0.w, acc[bi][3]);
                acc[bi][4] = fmaf(v, w1.x, acc[bi][4]);
                acc[bi][5] = fmaf(v, w1.y, acc[bi][5]);
                acc[bi][6] = fmaf(v, w1.z, acc[bi][6]);
                acc[bi][7] = fmaf(v, w1.w, acc[bi][7]);
            }
        }
        // z += h_{t-1} @ Wr
#pragma unroll 4
        for (int k = 0; k < H; k++) {
            float4 w0 = *(const float4*)(wr + k * NG);
            float4 w1 = *(const float4*)(wr + k * NG + 4);
#pragma unroll
            for (int bi = 0; bi < BPT; bi++) {
                float v = sH[(tb * BPT + bi) * HS + k];
                acc[bi][0] = fmaf(v, w0.x, acc[bi][0]);
                acc[bi][1] = fmaf(v, w0.y, acc[bi][1]);
                acc[bi][2] = fmaf(v, w0.z, acc[bi][2]);
                acc[bi][3] = fmaf(v, w0.w, acc[bi][3]);
                acc[bi][4] = fmaf(v, w1.x, acc[bi][4]);
                acc[bi][5] = fmaf(v, w1.y, acc[bi][5]);
                acc[bi][6] = fmaf(v, w1.z, acc[bi][6]);
                acc[bi][7] = fmaf(v, w1.w, acc[bi][7]);
            }
        }
        __syncthreads();   // everyone done reading old sH / sX

        // gates: [i, f, g, o] per hidden unit; update c (regs) and h (smem/out)
#pragma unroll
        for (int bi = 0; bi < BPT; bi++) {
            const int b = tb * BPT + bi;
            float h2[2];
#pragma unroll
            for (int jj = 0; jj < 2; jj++) {
                float zi = acc[bi][jj * 4 + 0];
                float zf = acc[bi][jj * 4 + 1];
                float zg = acc[bi][jj * 4 + 2];
                float zo = acc[bi][jj * 4 + 3];
                float cc = fsig(zf) * cst[bi][jj] + fsig(zi) * ftanh(zg);
                cst[bi][jj] = cc;
                h2[jj] = fsig(zo) * ftanh(cc);
                sH[b * HS + jh0 + jj] = h2[jj];
            }
            float2 hv = make_float2(h2[0], h2[1]);
            *(float2*)(out + ((size_t)(b0 + b) * TSEQ + t) * (2 * H)
                           + (fwd ? 0 : H) + jh0) = hv;
        }
        __syncthreads();   // new sH published before next step's GEMM
    }
}

// Layer 4 (D=32, H=4, return final state only): one thread per (batch row,
// direction). h, c, and all 16 gate accumulators live in registers; Wk/Wr
// broadcast from smem; x double-buffered in registers (prefetch t+1 during
// compute of t). No __syncthreads in the time loop.
__global__ void __launch_bounds__(64)
lstm_l4(const float* __restrict__ WkF, const float* __restrict__ WrF, const float* __restrict__ bF,
        const float* __restrict__ WkB, const float* __restrict__ WrB, const float* __restrict__ bB)
{
    const float* in = d_seq1;        // L3 output, [B][T][32]
    const int tid = threadIdx.x;
    const bool fwd = (blockIdx.y == 0);
    const int row = blockIdx.x * 64 + tid;

    __shared__ alignas(16) float sWk[32 * 16];   // permuted [k][j*4+g]
    __shared__ alignas(16) float sWr[4 * 16];
    __shared__ alignas(16) float sB[16];

    const float* Wk = fwd ? WkF : WkB;
    const float* Wr = fwd ? WrF : WrB;
    const float* bv = fwd ? bF  : bB;

    for (int i = tid; i < 32 * 16; i += 64) {
        int k = i >> 4, col = i & 15;
        sWk[i] = Wk[k * 16 + (col & 3) * 4 + (col >> 2)];
    }
    {
        int i = tid;
        if (i < 4 * 16) {
            int k = i >> 4, col = i & 15;
            sWr[i] = Wr[k * 16 + (col & 3) * 4 + (col >> 2)];
        }
        if (i < 16) sB[i] = bv[(i & 3) * 4 + (i >> 2)];
    }
    __syncthreads();

    float bj[16];
#pragma unroll
    for (int q = 0; q < 16; q++) bj[q] = sB[q];

    float h[4], c[4];
#pragma unroll
    for (int j = 0; j < 4; j++) { h[j] = 0.0f; c[j] = 0.0f; }

    const float* base = in + (size_t)row * TSEQ * 32;
    float4 xa[8], xb[8];
    {
        const float4* p = (const float4*)(base + (fwd ? 0 : (TSEQ - 1)) * 32);
#pragma unroll
        for (int i = 0; i < 8; i++) xa[i] = p[i];
    }

#pragma unroll 1
    for (int s = 0; s < TSEQ; s++) {
        // prefetch x_{t+1}
        if (s + 1 < TSEQ) {
            const int tn = fwd ? (s + 1) : (TSEQ - 2 - s);
            const float4* p = (const float4*)(base + tn * 32);
#pragma unroll
            for (int i = 0; i < 8; i++) xb[i] = p[i];
        }

        float z[16];
#pragma unroll
        for (int q = 0; q < 16; q++) z[q] = bj[q];

#pragma unroll
        for (int k = 0; k < 32; k++) {
            float v = ((const float*)xa)[k];
            const float4* wp = (const float4*)(sWk + k * 16);
            float4 w0 = wp[0], w1 = wp[1], w2 = wp[2], w3 = wp[3];
            z[0]  = fmaf(v, w0.x, z[0]);   z[1]  = fmaf(v, w0.y, z[1]);
            z[2]  = fmaf(v, w0.z, z[2]);   z[3]  = fmaf(v, w0.w, z[3]);
            z[4]  = fmaf(v, w1.x, z[4]);   z[5]  = fmaf(v, w1.y, z[5]);
            z[6]  = fmaf(v, w1.z, z[6]);   z[7]  = fmaf(v, w1.w, z[7]);
            z[8]  = fmaf(v, w2.x, z[8]);   z[9]  = fmaf(v, w2.y, z[9]);
            z[10] = fmaf(v, w2.z, z[10]);  z[11] = fmaf(v, w2.w, z[11]);
            z[12] = fmaf(v, w3.x, z[12]);  z[13] = fmaf(v, w3.y, z[13]);
            z[14] = fmaf(v, w3.z, z[14]);  z[15] = fmaf(v, w3.w, z[15]);
        }
#pragma unroll
        for (int k = 0; k < 4; k++) {
            float v = h[k];
            const float4* wp = (const float4*)(sWr + k * 16);
            float4 w0 = wp[0], w1 = wp[1], w2 = wp[2], w3 = wp[3];
            z[0]  = fmaf(v, w0.x, z[0]);   z[1]  = fmaf(v, w0.y, z[1]);
            z[2]  = fmaf(v, w0.z, z[2]);   z[3]  = fmaf(v, w0.w, z[3]);
            z[4]  = fmaf(v, w1.x, z[4]);   z[5]  = fmaf(v, w1.y, z[5]);
            z[6]  = fmaf(v, w1.z, z[6]);   z[7]  = fmaf(v, w1.w, z[7]);
            z[8]  = fmaf(v, w2.x, z[8]);   z[9]  = fmaf(v, w2.y, z[9]);
            z[10] = fmaf(v, w2.z, z[10]);  z[11] = fmaf(v, w2.w, z[11]);
            z[12] = fmaf(v, w3.x, z[12]);  z[13] = fmaf(v, w3.y, z[13]);
            z[14] = fmaf(v, w3.z, z[14]);  z[15] = fmaf(v, w3.w, z[15]);
        }

        // gate layout per hidden unit j: cols j*4 + {i,f,g,o}
#pragma unroll
        for (int j = 0; j < 4; j++) {
            float zi = z[j * 4 + 0];
            float zf = z[j * 4 + 1];
            float zg = z[j * 4 + 2];
            float zo = z[j * 4 + 3];
            float cc = fsig(zf) * c[j] + fsig(zi) * ftanh(zg);
            c[j] = cc;
            h[j] = fsig(zo) * ftanh(cc);
        }

#pragma unroll
        for (int i = 0; i < 8; i++) xa[i] = xb[i];
    }

    float4 hv = make_float4(h[0], h[1], h[2], h[3]);
    *(float4*)(d_h4 + (size_t)row * 8 + (fwd ? 0 : 4)) = hv;
}

__global__ void dense_sig(const float* __restrict__ W,
                          const float* __restrict__ bb, float* __restrict__ out)
{
    int b = blockIdx.x * blockDim.x + threadIdx.x;
    if (b >= BATCH) return;
    const float* hr = d_h4 + (size_t)b * 8;
    float hv[8];
#pragma unroll
    for (int j = 0; j < 8; j++) hv[j] = hr[j];
#pragma unroll
    for (int m = 0; m < 3; m++) {
        float a = bb[m];
#pragma unroll
        for (int j = 0; j < 8; j++) a = fmaf(hv[j], W[j * 3 + m], a);
        out[(size_t)b * 3 + m] = fsig(a);
    }
}

static size_t smem_bytes(int D, int H, int BT) {
    int NG = 4 * H;
    int DS = (D % 2 == 0) ? D + 1 : D;
    int HS = H + 1;
    return (size_t)(D * NG + H * NG + NG + BT * HS + BT * DS) * sizeof(float);
}

extern "C" void kernel_launch(void* const* d_in, const int* in_sizes, int n_in,
                              void* d_out, int out_size)
{
    (void)in_sizes; (void)n_in; (void)out_size;
    float* x = (float*)d_in[0];
    // layer param order per layer: Wk, Wr, b for f then b
    const float* p[24];
    for (int i = 0; i < 24; i++) p[i] = (const float*)d_in[1 + i];
    const float* dW = (const float*)d_in[25];
    const float* db = (const float*)d_in[26];

    size_t s1 = smem_bytes(78, 64, 64);
    size_t s2 = smem_bytes(128, 32, 64);
    size_t s3 = smem_bytes(64, 16, 64);
    cudaFuncSetAttribute(lstm_layer<78, 64, 64, 8, 0, 1>,
                         cudaFuncAttributeMaxDynamicSharedMemorySize, (int)s1);
    cudaFuncSetAttribute(lstm_layer<128, 32, 64, 4, 1, 2>,
                         cudaFuncAttributeMaxDynamicSharedMemorySize, (int)s2);
    cudaFuncSetAttribute(lstm_layer<64, 16, 64, 2, 2, 3>,
                         cudaFuncAttributeMaxDynamicSharedMemorySize, (int)s3);

    // L1: x -> seq1 (78 -> 2*64), grid (64,2), 256 thr
    lstm_layer<78, 64, 64, 8, 0, 1><<<dim3(BATCH / 64, 2), 256, s1>>>(
        x, nullptr, p[0], p[1], p[2], p[3], p[4], p[5]);
    // L2: seq1 -> seq2 (128 -> 2*32)
    lstm_layer<128, 32, 64, 4, 1, 2><<<dim3(BATCH / 64, 2), 256, s2>>>(
        nullptr, nullptr, p[6], p[7], p[8], p[9], p[10], p[11]);
    // L3: seq2 -> seq3(=seq1 front) (64 -> 2*16)
    lstm_layer<64, 16, 64, 2, 2, 3><<<dim3(BATCH / 64, 2), 256, s3>>>(
        nullptr, nullptr, p[12], p[13], p[14], p[15], p[16], p[17]);
    // L4: seq3 -> h4 final states [B,8], register-resident, sync-free
    lstm_l4<<<dim3(BATCH / 64, 2), 64>>>(p[18], p[19], p[20], p[21], p[22], p[23]);
    // dense 8->3 + sigmoid
    dense_sig<<<(BATCH + 255) / 256, 256>>>(dW, db, (float*)d_out);
}